// round 7
// baseline (speedup 1.0000x reference)
#include <cuda_runtime.h>
#include <cuda_bf16.h>
#include <math.h>
#include <stdint.h>

#define BATCH  4
#define CH     256
#define NGROUP 32
#define HW     4096
#define GEPS   1e-6f
#define STAGES 4

typedef __nv_bfloat16 bf16;

// ---------------- scratch (device globals; no allocation allowed) -------------
__device__ bf16  g_ofT[(size_t)BATCH * HW * CH];   // GN output, transposed [b][i][c]
__device__ bf16  g_q  [(size_t)BATCH * HW * CH];   // Q  [b][i][c]
__device__ bf16  g_k  [(size_t)BATCH * HW * CH];   // K  [b][j][c]
__device__ bf16  g_v  [(size_t)BATCH * CH * HW];   // V  [b][c][j]
__device__ bf16  g_atT[(size_t)BATCH * HW * CH];   // attn out transposed [b][i][c]
__device__ bf16  g_w16[4 * CH * CH];               // bf16 weights: wq|wk|wv|wp
__device__ float g_mean[BATCH * NGROUP];
__device__ float g_rstd[BATCH * NGROUP];

// ---------------- GroupNorm: stats --------------------------------------------
__global__ void __launch_bounds__(256) gn_stats(const float* __restrict__ x) {
    const int bg = blockIdx.x;
    const float* p = x + (size_t)bg * (CH / NGROUP) * HW;
    const int tid = threadIdx.x;

    float s = 0.f, s2 = 0.f;
    const int n4 = (CH / NGROUP) * HW / 4;
    for (int i = tid; i < n4; i += 256) {
        float4 v = ((const float4*)p)[i];
        s  += v.x + v.y + v.z + v.w;
        s2 += v.x * v.x + v.y * v.y + v.z * v.z + v.w * v.w;
    }
    __shared__ float red[64];
    #pragma unroll
    for (int o = 16; o; o >>= 1) {
        s  += __shfl_xor_sync(0xffffffffu, s,  o);
        s2 += __shfl_xor_sync(0xffffffffu, s2, o);
    }
    if ((tid & 31) == 0) { red[tid >> 5] = s; red[32 + (tid >> 5)] = s2; }
    __syncthreads();
    if (tid == 0) {
        float ts = 0.f, ts2 = 0.f;
        #pragma unroll
        for (int w = 0; w < 8; w++) { ts += red[w]; ts2 += red[32 + w]; }
        const float inv_n = 1.0f / ((CH / NGROUP) * HW);
        float mean = ts * inv_n;
        float var  = ts2 * inv_n - mean * mean;
        g_mean[bg] = mean;
        g_rstd[bg] = rsqrtf(var + GEPS);
    }
}

// ---------------- GroupNorm apply + transpose -> bf16 OF^T [b][i][c] -----------
__global__ void __launch_bounds__(256) gn_apply_t(const float* __restrict__ x,
                                                  const float* __restrict__ gs,
                                                  const float* __restrict__ gb) {
    __shared__ float tile[32][33];
    const int i0 = blockIdx.x * 32, c0 = blockIdx.y * 32, b = blockIdx.z;
    const int tx = threadIdx.x, ty = threadIdx.y;

    #pragma unroll
    for (int dy = 0; dy < 4; dy++) {
        int c = c0 + ty + dy * 8;
        int bg = b * NGROUP + (c >> 3);
        float r = g_rstd[bg];
        float a = gs[c] * r;
        float t = gb[c] - g_mean[bg] * a;
        float v = x[((size_t)b * CH + c) * HW + i0 + tx];
        tile[ty + dy * 8][tx] = v * a + t;
    }
    __syncthreads();

    const int tid = ty * 32 + tx;
    #pragma unroll
    for (int h = 0; h < 2; h++) {
        int p = tid + h * 256;
        int il = p >> 4, cl = (p & 15) * 2;
        __nv_bfloat162 o;
        o.x = __float2bfloat16_rn(tile[cl][il]);
        o.y = __float2bfloat16_rn(tile[cl + 1][il]);
        *(__nv_bfloat162*)(&g_ofT[((size_t)b * HW + i0 + il) * CH + c0 + cl]) = o;
    }
}

// ---------------- weights -> bf16 ----------------------------------------------
__global__ void __launch_bounds__(256) conv_w(const float* __restrict__ wq,
                                              const float* __restrict__ wk,
                                              const float* __restrict__ wv,
                                              const float* __restrict__ wp) {
    int i = blockIdx.x * 256 + threadIdx.x;
    if (i >= CH * CH) return;
    g_w16[0 * CH * CH + i] = __float2bfloat16_rn(wq[i]);
    g_w16[1 * CH * CH + i] = __float2bfloat16_rn(wk[i]);
    g_w16[2 * CH * CH + i] = __float2bfloat16_rn(wv[i]);
    g_w16[3 * CH * CH + i] = __float2bfloat16_rn(wp[i]);
}

// ---------------- shared PTX helpers --------------------------------------------
__device__ __forceinline__ unsigned swz(int m, int c) {  // 16B-chunk index in [128][32]bf16 page
    return (unsigned)((m << 2) + (c ^ ((m >> 1) & 3)));
}

#define CP16(dst_u32, src_ptr) \
    asm volatile("cp.async.cg.shared.global [%0], [%1], 16;\n" :: "r"(dst_u32), "l"(src_ptr))
#define LDMX4(r0, r1, r2, r3, addr) \
    asm volatile("ldmatrix.sync.aligned.m8n8.x4.shared.b16 {%0,%1,%2,%3}, [%4];\n" \
                 : "=r"(r0), "=r"(r1), "=r"(r2), "=r"(r3) : "r"(addr))
#define MMA16816(c0, c1, c2, c3, a0, a1, a2, a3, b0, b1) \
    asm volatile("mma.sync.aligned.m16n8k16.row.col.f32.bf16.bf16.f32 " \
                 "{%0,%1,%2,%3}, {%4,%5,%6,%7}, {%8,%9}, {%0,%1,%2,%3};\n" \
                 : "+f"(c0), "+f"(c1), "+f"(c2), "+f"(c3) \
                 : "r"(a0), "r"(a1), "r"(a2), "r"(a3), "r"(b0), "r"(b1))
#define COMMIT() asm volatile("cp.async.commit_group;\n")
#define WAITG(n) asm volatile("cp.async.wait_group %0;\n" :: "n"(n))

// ---------------- bf16 tensor-core GEMM (mma.sync HMMA) -------------------------
// (proven R6 kernel; used for QKV projections and final proj)
#define GEMM_SMEM_BYTES (STAGES * 16384)

template<int EPI, bool DUAL>
__global__ void __launch_bounds__(128) mma_gemm(
    const bf16* __restrict__ A, const bf16* __restrict__ B,
    void* __restrict__ Dv, int M, int N, int K,
    long long sA, long long sB, long long sD, float scale,
    const float* __restrict__ bias, const float* __restrict__ resid,
    const bf16* __restrict__ B2 = nullptr, void* __restrict__ Dv2 = nullptr,
    const float* __restrict__ bias2 = nullptr)
{
    extern __shared__ __align__(16) unsigned char sm[];
    int bz = blockIdx.z;
    if (DUAL) {
        const int sel = bz >> 2;
        bz &= 3;
        if (sel) { B = B2; Dv = Dv2; bias = bias2; }
    }
    A += (size_t)bz * sA;
    B += (size_t)bz * sB;
    const int m0 = blockIdx.y * 128, n0 = blockIdx.x * 128;
    const int tid = threadIdx.x, lane = tid & 31, warp = tid >> 5;
    const int wm = warp >> 1, wn = warp & 1;

    const unsigned smbase = (unsigned)__cvta_generic_to_shared(sm);

    const int lm = tid >> 2, lc = tid & 3;
    const bf16* gA[4]; const bf16* gB[4];
    unsigned dA[4], dB[4];
    #pragma unroll
    for (int i = 0; i < 4; i++) {
        gA[i] = A + (size_t)(m0 + lm + 32 * i) * K + lc * 8;
        gB[i] = B + (size_t)(n0 + lm + 32 * i) * K + lc * 8;
        dA[i] = swz(lm + 32 * i, lc) * 16u;
        dB[i] = 8192u + swz(lm + 32 * i, lc) * 16u;
    }

    unsigned aOff[4], bOff[4];
    {
        int r = wm * 64 + (lane & 15);
        int c0 = lane >> 4;
        #pragma unroll
        for (int mt = 0; mt < 4; mt++) aOff[mt] = swz(r + mt * 16, c0) * 16u;
    }
    {
        int r = wn * 64 + ((lane >> 4) << 3) + (lane & 7);
        int c0 = (lane >> 3) & 1;
        #pragma unroll
        for (int p = 0; p < 4; p++) bOff[p] = 8192u + swz(r + p * 16, c0) * 16u;
    }

    float acc[4][8][4];
    #pragma unroll
    for (int i = 0; i < 4; i++)
        #pragma unroll
        for (int j = 0; j < 8; j++)
            #pragma unroll
            for (int r = 0; r < 4; r++) acc[i][j][r] = 0.f;

    const int iters = K >> 5;

    #pragma unroll
    for (int s = 0; s < STAGES - 1; ++s) {
        unsigned st = smbase + (unsigned)s * 16384u;
        int k0 = s << 5;
        #pragma unroll
        for (int i = 0; i < 4; i++) { CP16(st + dA[i], gA[i] + k0); CP16(st + dB[i], gB[i] + k0); }
        COMMIT();
    }

    for (int it = 0; it < iters; ++it) {
        WAITG(STAGES - 2);
        __syncthreads();
        {
            int pf = it + STAGES - 1;
            if (pf < iters) {
                unsigned st = smbase + (unsigned)(pf & (STAGES - 1)) * 16384u;
                int k0 = pf << 5;
                #pragma unroll
                for (int i = 0; i < 4; i++) { CP16(st + dA[i], gA[i] + k0); CP16(st + dB[i], gB[i] + k0); }
            }
            COMMIT();
        }

        const unsigned sb = smbase + (unsigned)(it & (STAGES - 1)) * 16384u;
        #pragma unroll
        for (int ks = 0; ks < 2; ++ks) {
            const unsigned kx = (unsigned)ks * 32u;
            unsigned a[4][4], b[4][4];
            #pragma unroll
            for (int mt = 0; mt < 4; mt++)
                LDMX4(a[mt][0], a[mt][1], a[mt][2], a[mt][3], sb + (aOff[mt] ^ kx));
            #pragma unroll
            for (int p = 0; p < 4; p++)
                LDMX4(b[p][0], b[p][1], b[p][2], b[p][3], sb + (bOff[p] ^ kx));

            #pragma unroll
            for (int mt = 0; mt < 4; mt++) {
                #pragma unroll
                for (int nt = 0; nt < 8; nt++) {
                    const int p = nt >> 1, h = (nt & 1) << 1;
                    MMA16816(acc[mt][nt][0], acc[mt][nt][1], acc[mt][nt][2], acc[mt][nt][3],
                             a[mt][0], a[mt][1], a[mt][2], a[mt][3],
                             b[p][h + 0], b[p][h + 1]);
                }
            }
        }
    }

    const int row = m0 + wm * 64 + (lane >> 2);
    const int col = n0 + wn * 64 + (lane & 3) * 2;

    if (EPI == 4) {
        float* D = (float*)Dv + (size_t)bz * sD;
        const float* R = resid + (size_t)bz * sD;
        #pragma unroll
        for (int mt = 0; mt < 4; mt++) {
            #pragma unroll
            for (int nt = 0; nt < 8; nt++) {
                int r = row + mt * 16, cc = col + nt * 8;
                float b0 = bias[r], b1 = bias[r + 8];
                float2 v0 = { acc[mt][nt][0] + b0, acc[mt][nt][1] + b0 };
                float2 v1 = { acc[mt][nt][2] + b1, acc[mt][nt][3] + b1 };
                float2 r0 = *(const float2*)(&R[(size_t)r * N + cc]);
                float2 r1 = *(const float2*)(&R[(size_t)(r + 8) * N + cc]);
                v0.x += r0.x; v0.y += r0.y; v1.x += r1.x; v1.y += r1.y;
                *(float2*)(&D[(size_t)r * N + cc])       = v0;
                *(float2*)(&D[(size_t)(r + 8) * N + cc]) = v1;
            }
        }
    } else {
        bf16* D = (bf16*)Dv + (size_t)bz * sD;
        #pragma unroll
        for (int mt = 0; mt < 4; mt++) {
            #pragma unroll
            for (int nt = 0; nt < 8; nt++) {
                int r = row + mt * 16, cc = col + nt * 8;
                float bn0 = 0.f, bn1 = 0.f, bm0 = 0.f, bm1 = 0.f;
                if (EPI == 1) { bn0 = bias[cc]; bn1 = bias[cc + 1]; }
                if (EPI == 2) { bm0 = bias[r];  bm1 = bias[r + 8]; }
                __nv_bfloat162 o0, o1;
                o0.x = __float2bfloat16_rn(acc[mt][nt][0] * scale + bn0 + bm0);
                o0.y = __float2bfloat16_rn(acc[mt][nt][1] * scale + bn1 + bm0);
                o1.x = __float2bfloat16_rn(acc[mt][nt][2] * scale + bn0 + bm1);
                o1.y = __float2bfloat16_rn(acc[mt][nt][3] * scale + bn1 + bm1);
                *(__nv_bfloat162*)(&D[(size_t)r * N + cc])       = o0;
                *(__nv_bfloat162*)(&D[(size_t)(r + 8) * N + cc]) = o1;
            }
        }
    }
}

// ================= flash attention ===============================================
// Per CTA: 128 Q rows (i0..i0+127) of one batch; stream 32 KV tiles of 128.
// 256 threads / 8 warps; warp w owns Q rows 16w..16w+15 (full rows -> warp-local softmax).
// smem: Q resident 8 pages (64KB) + 6-page cp.async ring (48KB). Page = [128][32] bf16 swizzled.
// Stream chunks per tile: 8 K pages (c-chunks) then 8 V pages (j-chunk x c-half).
// S (16x128 fp32/warp) in regs -> online softmax -> P fragments from regs -> O (16x256 fp32/warp).
#define FLASH_SMEM (8 * 8192 + 6 * 8192)
#define NTILES (HW / 128)
#define NCHUNK (NTILES * 16)

__global__ void __launch_bounds__(256) flash_attn(
    const bf16* __restrict__ Qg, const bf16* __restrict__ Kg,
    const bf16* __restrict__ Vg, bf16* __restrict__ Og)
{
    extern __shared__ __align__(16) unsigned char sm[];
    const unsigned smbase = (unsigned)__cvta_generic_to_shared(sm);
    const unsigned qbase = smbase;
    const unsigned ring  = smbase + 65536u;

    const int tid = threadIdx.x, lane = tid & 31, warp = tid >> 5;
    const int b = blockIdx.y, i0 = blockIdx.x * 128;
    const bf16* Q = Qg + (size_t)b * HW * CH;
    const bf16* K = Kg + (size_t)b * HW * CH;
    const bf16* V = Vg + (size_t)b * CH * HW;
    bf16* O = Og + (size_t)b * HW * CH;

    const int lrow = tid >> 1, lch = (tid & 1) * 2;   // cp.async assignment: 2 CP16/thread/page

    // ---- Q resident load (group 0) ----
    #pragma unroll
    for (int p = 0; p < 8; p++) {
        const bf16* src = Q + (size_t)(i0 + lrow) * CH + p * 32 + lch * 8;
        unsigned pg = qbase + (unsigned)p * 8192u;
        CP16(pg + swz(lrow, lch) * 16u, src);
        CP16(pg + swz(lrow, lch + 1) * 16u, src + 8);
    }
    COMMIT();

    // ---- stream chunk issuer (one group per chunk, uniform across threads) ----
    auto issue = [&](int n) {
        if (n < NCHUNK) {
            const int t = n >> 4, q = n & 15;
            const unsigned pg = ring + (unsigned)(n % 6) * 8192u;
            const bf16* src;
            if (q < 8) {
                src = K + (size_t)(t * 128 + lrow) * CH + q * 32 + lch * 8;
            } else {
                const int v = q - 8;
                src = V + (size_t)((v & 1) * 128 + lrow) * HW + t * 128 + (v >> 1) * 32 + lch * 8;
            }
            CP16(pg + swz(lrow, lch) * 16u, src);
            CP16(pg + swz(lrow, lch + 1) * 16u, src + 8);
        }
        COMMIT();
    };

    #pragma unroll
    for (int n = 0; n < 4; n++) issue(n);

    // ---- fragment offsets (within an 8KB page) ----
    const unsigned aQ = swz((warp << 4) + (lane & 15), lane >> 4) * 16u;
    unsigned bO[8];
    {
        int r = ((lane >> 4) << 3) + (lane & 7);
        int c0 = (lane >> 3) & 1;
        #pragma unroll
        for (int p = 0; p < 8; p++) bO[p] = swz(p * 16 + r, c0) * 16u;
    }

    float Oa[32][4];
    #pragma unroll
    for (int i = 0; i < 32; i++)
        #pragma unroll
        for (int r = 0; r < 4; r++) Oa[i][r] = 0.f;
    float m0 = -INFINITY, m1 = -INFINITY, l0 = 0.f, l1 = 0.f;

    for (int t = 0; t < NTILES; ++t) {
        float S[16][4];
        #pragma unroll
        for (int i = 0; i < 16; i++)
            #pragma unroll
            for (int r = 0; r < 4; r++) S[i][r] = 0.f;

        // ---- QK: 8 c-chunks ----
        for (int cc = 0; cc < 8; ++cc) {
            const int g = t * 16 + cc;
            issue(g + 4);
            WAITG(4);
            __syncthreads();
            const unsigned kp = ring + (unsigned)(g % 6) * 8192u;
            const unsigned qp = qbase + (unsigned)cc * 8192u;
            #pragma unroll
            for (int ks = 0; ks < 2; ++ks) {
                const unsigned kx = (unsigned)ks * 32u;
                unsigned a[4];
                LDMX4(a[0], a[1], a[2], a[3], qp + (aQ ^ kx));
                #pragma unroll
                for (int p = 0; p < 8; p++) {
                    unsigned bb[4];
                    LDMX4(bb[0], bb[1], bb[2], bb[3], kp + (bO[p] ^ kx));
                    MMA16816(S[2*p][0], S[2*p][1], S[2*p][2], S[2*p][3],
                             a[0], a[1], a[2], a[3], bb[0], bb[1]);
                    MMA16816(S[2*p+1][0], S[2*p+1][1], S[2*p+1][2], S[2*p+1][3],
                             a[0], a[1], a[2], a[3], bb[2], bb[3]);
                }
            }
        }

        // ---- online softmax (warp-local; quad lanes share a row) ----
        float mx0 = -INFINITY, mx1 = -INFINITY;
        #pragma unroll
        for (int i = 0; i < 16; i++) {
            S[i][0] *= 0.0625f; S[i][1] *= 0.0625f; S[i][2] *= 0.0625f; S[i][3] *= 0.0625f;
            mx0 = fmaxf(mx0, fmaxf(S[i][0], S[i][1]));
            mx1 = fmaxf(mx1, fmaxf(S[i][2], S[i][3]));
        }
        mx0 = fmaxf(mx0, __shfl_xor_sync(0xffffffffu, mx0, 1));
        mx0 = fmaxf(mx0, __shfl_xor_sync(0xffffffffu, mx0, 2));
        mx1 = fmaxf(mx1, __shfl_xor_sync(0xffffffffu, mx1, 1));
        mx1 = fmaxf(mx1, __shfl_xor_sync(0xffffffffu, mx1, 2));
        const float mn0 = fmaxf(m0, mx0), mn1 = fmaxf(m1, mx1);
        const float al0 = __expf(m0 - mn0), al1 = __expf(m1 - mn1);
        float s0 = 0.f, s1 = 0.f;
        #pragma unroll
        for (int i = 0; i < 16; i++) {
            S[i][0] = __expf(S[i][0] - mn0); S[i][1] = __expf(S[i][1] - mn0);
            S[i][2] = __expf(S[i][2] - mn1); S[i][3] = __expf(S[i][3] - mn1);
            s0 += S[i][0] + S[i][1];
            s1 += S[i][2] + S[i][3];
        }
        s0 += __shfl_xor_sync(0xffffffffu, s0, 1); s0 += __shfl_xor_sync(0xffffffffu, s0, 2);
        s1 += __shfl_xor_sync(0xffffffffu, s1, 1); s1 += __shfl_xor_sync(0xffffffffu, s1, 2);
        l0 = l0 * al0 + s0;  l1 = l1 * al1 + s1;
        m0 = mn0;  m1 = mn1;
        #pragma unroll
        for (int i = 0; i < 32; i++) {
            Oa[i][0] *= al0; Oa[i][1] *= al0;
            Oa[i][2] *= al1; Oa[i][3] *= al1;
        }

        // ---- pack P fragments from S regs (C-layout == A-layout identity) ----
        unsigned aP[8][4];
        #pragma unroll
        for (int kc = 0; kc < 8; kc++) {
            __nv_bfloat162 h0 = __floats2bfloat162_rn(S[2*kc][0],   S[2*kc][1]);
            __nv_bfloat162 h1 = __floats2bfloat162_rn(S[2*kc][2],   S[2*kc][3]);
            __nv_bfloat162 h2 = __floats2bfloat162_rn(S[2*kc+1][0], S[2*kc+1][1]);
            __nv_bfloat162 h3 = __floats2bfloat162_rn(S[2*kc+1][2], S[2*kc+1][3]);
            aP[kc][0] = *(unsigned*)&h0; aP[kc][1] = *(unsigned*)&h1;
            aP[kc][2] = *(unsigned*)&h2; aP[kc][3] = *(unsigned*)&h3;
        }

        // ---- PV: 4 j-chunks x 2 c-half pages ----
        for (int jc = 0; jc < 4; ++jc) {
            const int g1 = t * 16 + 8 + 2 * jc, g2 = g1 + 1;
            issue(g1 + 4);
            issue(g2 + 4);
            WAITG(4);
            __syncthreads();
            const unsigned vp0 = ring + (unsigned)(g1 % 6) * 8192u;
            const unsigned vp1 = ring + (unsigned)(g2 % 6) * 8192u;
            #pragma unroll
            for (int ks = 0; ks < 2; ++ks) {
                const unsigned kx = (unsigned)ks * 32u;
                const int kc = jc * 2 + ks;
                #pragma unroll
                for (int h = 0; h < 2; h++) {
                    const unsigned vp = h ? vp1 : vp0;
                    #pragma unroll
                    for (int p = 0; p < 8; p++) {
                        unsigned bb[4];
                        LDMX4(bb[0], bb[1], bb[2], bb[3], vp + (bO[p] ^ kx));
                        const int nt = h * 16 + 2 * p;
                        MMA16816(Oa[nt][0], Oa[nt][1], Oa[nt][2], Oa[nt][3],
                                 aP[kc][0], aP[kc][1], aP[kc][2], aP[kc][3], bb[0], bb[1]);
                        MMA16816(Oa[nt+1][0], Oa[nt+1][1], Oa[nt+1][2], Oa[nt+1][3],
                                 aP[kc][0], aP[kc][1], aP[kc][2], aP[kc][3], bb[2], bb[3]);
                    }
                }
            }
        }
    }

    // ---- epilogue: O /= l, write atT[i][c] bf16 ----
    const float inv0 = 1.0f / l0, inv1 = 1.0f / l1;
    const int rowA = i0 + warp * 16 + (lane >> 2);
    const int col0 = (lane & 3) * 2;
    #pragma unroll
    for (int nt = 0; nt < 32; nt++) {
        const int c = nt * 8 + col0;
        __nv_bfloat162 oA = __floats2bfloat162_rn(Oa[nt][0] * inv0, Oa[nt][1] * inv0);
        __nv_bfloat162 oB = __floats2bfloat162_rn(Oa[nt][2] * inv1, Oa[nt][3] * inv1);
        *(__nv_bfloat162*)(&O[(size_t)rowA * CH + c])       = oA;
        *(__nv_bfloat162*)(&O[(size_t)(rowA + 8) * CH + c]) = oB;
    }
}

// ---------------- launch --------------------------------------------------------
extern "C" void kernel_launch(void* const* d_in, const int* in_sizes, int n_in,
                              void* d_out, int out_size) {
    const float* x  = (const float*)d_in[0];
    const float* gs = (const float*)d_in[1];
    const float* gb = (const float*)d_in[2];
    const float* wq = (const float*)d_in[3];
    const float* bq = (const float*)d_in[4];
    const float* wk = (const float*)d_in[5];
    const float* bk = (const float*)d_in[6];
    const float* wv = (const float*)d_in[7];
    const float* bv = (const float*)d_in[8];
    const float* wp = (const float*)d_in[9];
    const float* bp = (const float*)d_in[10];
    float* out = (float*)d_out;

    bf16 *p_ofT, *p_q, *p_k, *p_v, *p_atT, *p_w16;
    cudaGetSymbolAddress((void**)&p_ofT, g_ofT);
    cudaGetSymbolAddress((void**)&p_q,   g_q);
    cudaGetSymbolAddress((void**)&p_k,   g_k);
    cudaGetSymbolAddress((void**)&p_v,   g_v);
    cudaGetSymbolAddress((void**)&p_atT, g_atT);
    cudaGetSymbolAddress((void**)&p_w16, g_w16);

    cudaFuncSetAttribute(mma_gemm<1, true >, cudaFuncAttributeMaxDynamicSharedMemorySize, GEMM_SMEM_BYTES);
    cudaFuncSetAttribute(mma_gemm<2, false>, cudaFuncAttributeMaxDynamicSharedMemorySize, GEMM_SMEM_BYTES);
    cudaFuncSetAttribute(mma_gemm<4, false>, cudaFuncAttributeMaxDynamicSharedMemorySize, GEMM_SMEM_BYTES);
    cudaFuncSetAttribute(flash_attn, cudaFuncAttributeMaxDynamicSharedMemorySize, FLASH_SMEM);

    const long long sIC = (long long)HW * CH;   // [i][c] per-batch stride
    const long long sCI = (long long)CH * HW;   // [c][i] per-batch stride

    // 1) GroupNorm + weight conversion
    gn_stats<<<BATCH * NGROUP, 256>>>(x);
    conv_w<<<CH * CH / 256, 256>>>(wq, wk, wv, wp);
    gn_apply_t<<<dim3(HW / 32, CH / 32, BATCH), dim3(32, 8)>>>(x, gs, gb);

    // 2) Q and K fused in one launch (grid.z = 8; z>>2 selects weight/bias/dst)
    dim3 gQK(CH / 128, HW / 128, 2 * BATCH);
    mma_gemm<1, true><<<gQK, 128, GEMM_SMEM_BYTES>>>(
        p_ofT, p_w16 + 0 * CH * CH, p_q, HW, CH, CH, sIC, 0, sIC, 1.0f, bq, nullptr,
        p_w16 + 1 * CH * CH, p_k, bk);
    // V: [c][j] = W x OF + bias[m]
    dim3 gV(HW / 128, CH / 128, BATCH);
    mma_gemm<2, false><<<gV, 128, GEMM_SMEM_BYTES>>>(p_w16 + 2 * CH * CH, p_ofT, p_v, CH, HW, CH, 0, sIC, sCI, 1.0f, bv, nullptr);

    // 3) fused attention: scores + softmax + P.V in one kernel -> atT[i][c]
    flash_attn<<<dim3(HW / 128, BATCH), 256, FLASH_SMEM>>>(p_q, p_k, p_v, p_atT);

    // 4) proj + bias + residual -> d_out
    dim3 gP(HW / 128, CH / 128, BATCH);
    mma_gemm<4, false><<<gP, 128, GEMM_SMEM_BYTES>>>(p_w16 + 3 * CH * CH, p_atT, out, CH, HW, CH, 0, sIC, sCI, 1.0f, bp, x);
}

// round 8
// speedup vs baseline: 1.0317x; 1.0317x over previous
#include <cuda_runtime.h>
#include <cuda_bf16.h>
#include <math.h>
#include <stdint.h>

#define BATCH  4
#define CH     256
#define NGROUP 32
#define HW     4096
#define GEPS   1e-6f
#define STAGES 4

typedef __nv_bfloat16 bf16;

// ---------------- scratch (device globals; no allocation allowed) -------------
__device__ bf16  g_ofT[(size_t)BATCH * HW * CH];   // GN output, transposed [b][i][c]
__device__ bf16  g_q  [(size_t)BATCH * HW * CH];   // Q  [b][i][c]
__device__ bf16  g_k  [(size_t)BATCH * HW * CH];   // K  [b][j][c]
__device__ bf16  g_v  [(size_t)BATCH * CH * HW];   // V  [b][c][j]
__device__ bf16  g_atT[(size_t)BATCH * HW * CH];   // attn out transposed [b][i][c]
__device__ bf16  g_s  [(size_t)BATCH * HW * HW];   // scores -> probs bf16 in place (134MB)
__device__ bf16  g_w16[4 * CH * CH];               // bf16 weights: wq|wk|wv|wp
__device__ float g_mean[BATCH * NGROUP];
__device__ float g_rstd[BATCH * NGROUP];

// ---------------- GroupNorm: stats --------------------------------------------
__global__ void __launch_bounds__(256) gn_stats(const float* __restrict__ x) {
    const int bg = blockIdx.x;
    const float* p = x + (size_t)bg * (CH / NGROUP) * HW;
    const int tid = threadIdx.x;

    float s = 0.f, s2 = 0.f;
    const int n4 = (CH / NGROUP) * HW / 4;
    for (int i = tid; i < n4; i += 256) {
        float4 v = ((const float4*)p)[i];
        s  += v.x + v.y + v.z + v.w;
        s2 += v.x * v.x + v.y * v.y + v.z * v.z + v.w * v.w;
    }
    __shared__ float red[64];
    #pragma unroll
    for (int o = 16; o; o >>= 1) {
        s  += __shfl_xor_sync(0xffffffffu, s,  o);
        s2 += __shfl_xor_sync(0xffffffffu, s2, o);
    }
    if ((tid & 31) == 0) { red[tid >> 5] = s; red[32 + (tid >> 5)] = s2; }
    __syncthreads();
    if (tid == 0) {
        float ts = 0.f, ts2 = 0.f;
        #pragma unroll
        for (int w = 0; w < 8; w++) { ts += red[w]; ts2 += red[32 + w]; }
        const float inv_n = 1.0f / ((CH / NGROUP) * HW);
        float mean = ts * inv_n;
        float var  = ts2 * inv_n - mean * mean;
        g_mean[bg] = mean;
        g_rstd[bg] = rsqrtf(var + GEPS);
    }
}

// ---------------- GroupNorm apply + transpose -> bf16 OF^T [b][i][c] -----------
__global__ void __launch_bounds__(256) gn_apply_t(const float* __restrict__ x,
                                                  const float* __restrict__ gs,
                                                  const float* __restrict__ gb) {
    __shared__ float tile[32][33];
    const int i0 = blockIdx.x * 32, c0 = blockIdx.y * 32, b = blockIdx.z;
    const int tx = threadIdx.x, ty = threadIdx.y;

    #pragma unroll
    for (int dy = 0; dy < 4; dy++) {
        int c = c0 + ty + dy * 8;
        int bg = b * NGROUP + (c >> 3);
        float r = g_rstd[bg];
        float a = gs[c] * r;
        float t = gb[c] - g_mean[bg] * a;
        float v = x[((size_t)b * CH + c) * HW + i0 + tx];
        tile[ty + dy * 8][tx] = v * a + t;
    }
    __syncthreads();

    const int tid = ty * 32 + tx;
    #pragma unroll
    for (int h = 0; h < 2; h++) {
        int p = tid + h * 256;
        int il = p >> 4, cl = (p & 15) * 2;
        __nv_bfloat162 o;
        o.x = __float2bfloat16_rn(tile[cl][il]);
        o.y = __float2bfloat16_rn(tile[cl + 1][il]);
        *(__nv_bfloat162*)(&g_ofT[((size_t)b * HW + i0 + il) * CH + c0 + cl]) = o;
    }
}

// ---------------- weights -> bf16 ----------------------------------------------
__global__ void __launch_bounds__(256) conv_w(const float* __restrict__ wq,
                                              const float* __restrict__ wk,
                                              const float* __restrict__ wv,
                                              const float* __restrict__ wp) {
    int i = blockIdx.x * 256 + threadIdx.x;
    if (i >= CH * CH) return;
    g_w16[0 * CH * CH + i] = __float2bfloat16_rn(wq[i]);
    g_w16[1 * CH * CH + i] = __float2bfloat16_rn(wk[i]);
    g_w16[2 * CH * CH + i] = __float2bfloat16_rn(wv[i]);
    g_w16[3 * CH * CH + i] = __float2bfloat16_rn(wp[i]);
}

// ---------------- shared PTX helpers --------------------------------------------
__device__ __forceinline__ unsigned swz(int m, int c) {  // 16B-chunk index, rows x 32 bf16 cols
    return (unsigned)((m << 2) + (c ^ ((m >> 1) & 3)));
}

#define CP16(dst_u32, src_ptr) \
    asm volatile("cp.async.cg.shared.global [%0], [%1], 16;\n" :: "r"(dst_u32), "l"(src_ptr))
#define LDMX4(r0, r1, r2, r3, addr) \
    asm volatile("ldmatrix.sync.aligned.m8n8.x4.shared.b16 {%0,%1,%2,%3}, [%4];\n" \
                 : "=r"(r0), "=r"(r1), "=r"(r2), "=r"(r3) : "r"(addr))
#define MMA16816(c0, c1, c2, c3, a0, a1, a2, a3, b0, b1) \
    asm volatile("mma.sync.aligned.m16n8k16.row.col.f32.bf16.bf16.f32 " \
                 "{%0,%1,%2,%3}, {%4,%5,%6,%7}, {%8,%9}, {%0,%1,%2,%3};\n" \
                 : "+f"(c0), "+f"(c1), "+f"(c2), "+f"(c3) \
                 : "r"(a0), "r"(a1), "r"(a2), "r"(a3), "r"(b0), "r"(b1))
#define COMMIT() asm volatile("cp.async.commit_group;\n")
#define WAITG(n) asm volatile("cp.async.wait_group %0;\n" :: "n"(n))

// ---------------- small-GEMM (CTA 128x128, 4 warps) -----------------------------
// Used for QKV projections and final proj (K=256). See R6.
#define GEMM_SMEM_BYTES (STAGES * 16384)

template<int EPI, bool DUAL>
__global__ void __launch_bounds__(128) mma_gemm(
    const bf16* __restrict__ A, const bf16* __restrict__ B,
    void* __restrict__ Dv, int M, int N, int K,
    long long sA, long long sB, long long sD, float scale,
    const float* __restrict__ bias, const float* __restrict__ resid,
    const bf16* __restrict__ B2 = nullptr, void* __restrict__ Dv2 = nullptr,
    const float* __restrict__ bias2 = nullptr)
{
    extern __shared__ __align__(16) unsigned char sm[];
    int bz = blockIdx.z;
    if (DUAL) {
        const int sel = bz >> 2;
        bz &= 3;
        if (sel) { B = B2; Dv = Dv2; bias = bias2; }
    }
    A += (size_t)bz * sA;
    B += (size_t)bz * sB;
    const int m0 = blockIdx.y * 128, n0 = blockIdx.x * 128;
    const int tid = threadIdx.x, lane = tid & 31, warp = tid >> 5;
    const int wm = warp >> 1, wn = warp & 1;

    const unsigned smbase = (unsigned)__cvta_generic_to_shared(sm);

    const int lm = tid >> 2, lc = tid & 3;
    const bf16* gA[4]; const bf16* gB[4];
    unsigned dA[4], dB[4];
    #pragma unroll
    for (int i = 0; i < 4; i++) {
        gA[i] = A + (size_t)(m0 + lm + 32 * i) * K + lc * 8;
        gB[i] = B + (size_t)(n0 + lm + 32 * i) * K + lc * 8;
        dA[i] = swz(lm + 32 * i, lc) * 16u;
        dB[i] = 8192u + swz(lm + 32 * i, lc) * 16u;
    }

    unsigned aOff[4], bOff[4];
    {
        int r = wm * 64 + (lane & 15);
        int c0 = lane >> 4;
        #pragma unroll
        for (int mt = 0; mt < 4; mt++) aOff[mt] = swz(r + mt * 16, c0) * 16u;
    }
    {
        int r = wn * 64 + ((lane >> 4) << 3) + (lane & 7);
        int c0 = (lane >> 3) & 1;
        #pragma unroll
        for (int p = 0; p < 4; p++) bOff[p] = 8192u + swz(r + p * 16, c0) * 16u;
    }

    float acc[4][8][4];
    #pragma unroll
    for (int i = 0; i < 4; i++)
        #pragma unroll
        for (int j = 0; j < 8; j++)
            #pragma unroll
            for (int r = 0; r < 4; r++) acc[i][j][r] = 0.f;

    const int iters = K >> 5;

    #pragma unroll
    for (int s = 0; s < STAGES - 1; ++s) {
        unsigned st = smbase + (unsigned)s * 16384u;
        int k0 = s << 5;
        #pragma unroll
        for (int i = 0; i < 4; i++) { CP16(st + dA[i], gA[i] + k0); CP16(st + dB[i], gB[i] + k0); }
        COMMIT();
    }

    for (int it = 0; it < iters; ++it) {
        WAITG(STAGES - 2);
        __syncthreads();
        {
            int pf = it + STAGES - 1;
            if (pf < iters) {
                unsigned st = smbase + (unsigned)(pf & (STAGES - 1)) * 16384u;
                int k0 = pf << 5;
                #pragma unroll
                for (int i = 0; i < 4; i++) { CP16(st + dA[i], gA[i] + k0); CP16(st + dB[i], gB[i] + k0); }
            }
            COMMIT();
        }

        const unsigned sb = smbase + (unsigned)(it & (STAGES - 1)) * 16384u;
        #pragma unroll
        for (int ks = 0; ks < 2; ++ks) {
            const unsigned kx = (unsigned)ks * 32u;
            unsigned a[4][4], b[4][4];
            #pragma unroll
            for (int mt = 0; mt < 4; mt++)
                LDMX4(a[mt][0], a[mt][1], a[mt][2], a[mt][3], sb + (aOff[mt] ^ kx));
            #pragma unroll
            for (int p = 0; p < 4; p++)
                LDMX4(b[p][0], b[p][1], b[p][2], b[p][3], sb + (bOff[p] ^ kx));

            #pragma unroll
            for (int mt = 0; mt < 4; mt++) {
                #pragma unroll
                for (int nt = 0; nt < 8; nt++) {
                    const int p = nt >> 1, h = (nt & 1) << 1;
                    MMA16816(acc[mt][nt][0], acc[mt][nt][1], acc[mt][nt][2], acc[mt][nt][3],
                             a[mt][0], a[mt][1], a[mt][2], a[mt][3],
                             b[p][h + 0], b[p][h + 1]);
                }
            }
        }
    }

    const int row = m0 + wm * 64 + (lane >> 2);
    const int col = n0 + wn * 64 + (lane & 3) * 2;

    if (EPI == 4) {
        float* D = (float*)Dv + (size_t)bz * sD;
        const float* R = resid + (size_t)bz * sD;
        #pragma unroll
        for (int mt = 0; mt < 4; mt++) {
            #pragma unroll
            for (int nt = 0; nt < 8; nt++) {
                int r = row + mt * 16, cc = col + nt * 8;
                float b0 = bias[r], b1 = bias[r + 8];
                float2 v0 = { acc[mt][nt][0] + b0, acc[mt][nt][1] + b0 };
                float2 v1 = { acc[mt][nt][2] + b1, acc[mt][nt][3] + b1 };
                float2 r0 = *(const float2*)(&R[(size_t)r * N + cc]);
                float2 r1 = *(const float2*)(&R[(size_t)(r + 8) * N + cc]);
                v0.x += r0.x; v0.y += r0.y; v1.x += r1.x; v1.y += r1.y;
                *(float2*)(&D[(size_t)r * N + cc])       = v0;
                *(float2*)(&D[(size_t)(r + 8) * N + cc]) = v1;
            }
        }
    } else {
        bf16* D = (bf16*)Dv + (size_t)bz * sD;
        #pragma unroll
        for (int mt = 0; mt < 4; mt++) {
            #pragma unroll
            for (int nt = 0; nt < 8; nt++) {
                int r = row + mt * 16, cc = col + nt * 8;
                float bn0 = 0.f, bn1 = 0.f, bm0 = 0.f, bm1 = 0.f;
                if (EPI == 1) { bn0 = bias[cc]; bn1 = bias[cc + 1]; }
                if (EPI == 2) { bm0 = bias[r];  bm1 = bias[r + 8]; }
                __nv_bfloat162 o0, o1;
                o0.x = __float2bfloat16_rn(acc[mt][nt][0] * scale + bn0 + bm0);
                o0.y = __float2bfloat16_rn(acc[mt][nt][1] * scale + bn1 + bm0);
                o1.x = __float2bfloat16_rn(acc[mt][nt][2] * scale + bn0 + bm1);
                o1.y = __float2bfloat16_rn(acc[mt][nt][3] * scale + bn1 + bm1);
                *(__nv_bfloat162*)(&D[(size_t)r * N + cc])       = o0;
                *(__nv_bfloat162*)(&D[(size_t)(r + 8) * N + cc]) = o1;
            }
        }
    }
}

// ---------------- big-GEMM: CTA 256x128, 8 warps (4m x 2n), warp 64x64 ----------
// D[m][n] = scale * sum_k A[m][k]*B[n][k], bf16 out. Stage: A 16KB + B 8KB = 24KB.
#define BIG_STAGE   24576
#define BIG_SMEM    (STAGES * BIG_STAGE)

__global__ void __launch_bounds__(256) mma_gemm_big(
    const bf16* __restrict__ A, const bf16* __restrict__ B,
    bf16* __restrict__ D, int M, int N, int K,
    long long sA, long long sB, long long sD, float scale)
{
    extern __shared__ __align__(16) unsigned char sm[];
    const int bz = blockIdx.z;
    A += (size_t)bz * sA;
    B += (size_t)bz * sB;
    D += (size_t)bz * sD;
    const int m0 = blockIdx.y * 256, n0 = blockIdx.x * 128;
    const int tid = threadIdx.x, lane = tid & 31, warp = tid >> 5;
    const int wm = warp >> 1, wn = warp & 1;

    const unsigned smbase = (unsigned)__cvta_generic_to_shared(sm);

    // global loads: lm = tid>>2 (0..63), lc = tid&3. A rows lm+64i (i<4), B rows lm+64i (i<2)
    const int lm = tid >> 2, lc = tid & 3;
    const bf16* gA[4]; const bf16* gB[2];
    unsigned dA[4], dB[2];
    #pragma unroll
    for (int i = 0; i < 4; i++) {
        gA[i] = A + (size_t)(m0 + lm + 64 * i) * K + lc * 8;
        dA[i] = swz(lm + 64 * i, lc) * 16u;
    }
    #pragma unroll
    for (int i = 0; i < 2; i++) {
        gB[i] = B + (size_t)(n0 + lm + 64 * i) * K + lc * 8;
        dB[i] = 16384u + swz(lm + 64 * i, lc) * 16u;
    }

    unsigned aOff[4], bOff[4];
    {
        int r = wm * 64 + (lane & 15);
        int c0 = lane >> 4;
        #pragma unroll
        for (int mt = 0; mt < 4; mt++) aOff[mt] = swz(r + mt * 16, c0) * 16u;
    }
    {
        int r = wn * 64 + ((lane >> 4) << 3) + (lane & 7);
        int c0 = (lane >> 3) & 1;
        #pragma unroll
        for (int p = 0; p < 4; p++) bOff[p] = 16384u + swz(r + p * 16, c0) * 16u;
    }

    float acc[4][8][4];
    #pragma unroll
    for (int i = 0; i < 4; i++)
        #pragma unroll
        for (int j = 0; j < 8; j++)
            #pragma unroll
            for (int r = 0; r < 4; r++) acc[i][j][r] = 0.f;

    const int iters = K >> 5;

    #pragma unroll
    for (int s = 0; s < STAGES - 1; ++s) {
        unsigned st = smbase + (unsigned)s * BIG_STAGE;
        int k0 = s << 5;
        #pragma unroll
        for (int i = 0; i < 4; i++) CP16(st + dA[i], gA[i] + k0);
        #pragma unroll
        for (int i = 0; i < 2; i++) CP16(st + dB[i], gB[i] + k0);
        COMMIT();
    }

    for (int it = 0; it < iters; ++it) {
        WAITG(STAGES - 2);
        __syncthreads();
        {
            int pf = it + STAGES - 1;
            if (pf < iters) {
                unsigned st = smbase + (unsigned)((pf & (STAGES - 1))) * BIG_STAGE;
                int k0 = pf << 5;
                #pragma unroll
                for (int i = 0; i < 4; i++) CP16(st + dA[i], gA[i] + k0);
                #pragma unroll
                for (int i = 0; i < 2; i++) CP16(st + dB[i], gB[i] + k0);
            }
            COMMIT();
        }

        const unsigned sb = smbase + (unsigned)(it & (STAGES - 1)) * BIG_STAGE;
        #pragma unroll
        for (int ks = 0; ks < 2; ++ks) {
            const unsigned kx = (unsigned)ks * 32u;
            unsigned a[4][4], b[4][4];
            #pragma unroll
            for (int mt = 0; mt < 4; mt++)
                LDMX4(a[mt][0], a[mt][1], a[mt][2], a[mt][3], sb + (aOff[mt] ^ kx));
            #pragma unroll
            for (int p = 0; p < 4; p++)
                LDMX4(b[p][0], b[p][1], b[p][2], b[p][3], sb + (bOff[p] ^ kx));

            #pragma unroll
            for (int mt = 0; mt < 4; mt++) {
                #pragma unroll
                for (int nt = 0; nt < 8; nt++) {
                    const int p = nt >> 1, h = (nt & 1) << 1;
                    MMA16816(acc[mt][nt][0], acc[mt][nt][1], acc[mt][nt][2], acc[mt][nt][3],
                             a[mt][0], a[mt][1], a[mt][2], a[mt][3],
                             b[p][h + 0], b[p][h + 1]);
                }
            }
        }
    }

    const int row = m0 + wm * 64 + (lane >> 2);
    const int col = n0 + wn * 64 + (lane & 3) * 2;
    #pragma unroll
    for (int mt = 0; mt < 4; mt++) {
        #pragma unroll
        for (int nt = 0; nt < 8; nt++) {
            int r = row + mt * 16, cc = col + nt * 8;
            __nv_bfloat162 o0, o1;
            o0.x = __float2bfloat16_rn(acc[mt][nt][0] * scale);
            o0.y = __float2bfloat16_rn(acc[mt][nt][1] * scale);
            o1.x = __float2bfloat16_rn(acc[mt][nt][2] * scale);
            o1.y = __float2bfloat16_rn(acc[mt][nt][3] * scale);
            *(__nv_bfloat162*)(&D[(size_t)r * N + cc])       = o0;
            *(__nv_bfloat162*)(&D[(size_t)(r + 8) * N + cc]) = o1;
        }
    }
}

// ---------------- row softmax, bf16 in place -------------------------------------
__global__ void __launch_bounds__(256) softmax_rows(bf16* __restrict__ S) {
    const int i = blockIdx.x, b = blockIdx.y;
    bf16* p = S + ((size_t)b * HW + i) * HW;
    const int tid = threadIdx.x;
    __shared__ float red[32];

    bf16 v[16];
    *(uint4*)(v)     = ((const uint4*)p)[tid];
    *(uint4*)(v + 8) = ((const uint4*)p)[tid + 256];
    float f[16];
    float mx = -INFINITY;
    #pragma unroll
    for (int t = 0; t < 16; t++) { f[t] = __bfloat162float(v[t]); mx = fmaxf(mx, f[t]); }
    #pragma unroll
    for (int o = 16; o; o >>= 1) mx = fmaxf(mx, __shfl_xor_sync(0xffffffffu, mx, o));
    if ((tid & 31) == 0) red[tid >> 5] = mx;
    __syncthreads();
    mx = red[0];
    #pragma unroll
    for (int w = 1; w < 8; w++) mx = fmaxf(mx, red[w]);
    __syncthreads();

    float s = 0.f;
    #pragma unroll
    for (int t = 0; t < 16; t++) { f[t] = __expf(f[t] - mx); s += f[t]; }
    #pragma unroll
    for (int o = 16; o; o >>= 1) s += __shfl_xor_sync(0xffffffffu, s, o);
    if ((tid & 31) == 0) red[tid >> 5] = s;
    __syncthreads();
    s = 0.f;
    #pragma unroll
    for (int w = 0; w < 8; w++) s += red[w];
    const float inv = 1.0f / s;
    #pragma unroll
    for (int t = 0; t < 16; t++) v[t] = __float2bfloat16_rn(f[t] * inv);
    ((uint4*)p)[tid]       = *(uint4*)(v);
    ((uint4*)p)[tid + 256] = *(uint4*)(v + 8);
}

// ---------------- launch --------------------------------------------------------
extern "C" void kernel_launch(void* const* d_in, const int* in_sizes, int n_in,
                              void* d_out, int out_size) {
    const float* x  = (const float*)d_in[0];
    const float* gs = (const float*)d_in[1];
    const float* gb = (const float*)d_in[2];
    const float* wq = (const float*)d_in[3];
    const float* bq = (const float*)d_in[4];
    const float* wk = (const float*)d_in[5];
    const float* bk = (const float*)d_in[6];
    const float* wv = (const float*)d_in[7];
    const float* bv = (const float*)d_in[8];
    const float* wp = (const float*)d_in[9];
    const float* bp = (const float*)d_in[10];
    float* out = (float*)d_out;

    bf16 *p_ofT, *p_q, *p_k, *p_v, *p_atT, *p_s, *p_w16;
    cudaGetSymbolAddress((void**)&p_ofT, g_ofT);
    cudaGetSymbolAddress((void**)&p_q,   g_q);
    cudaGetSymbolAddress((void**)&p_k,   g_k);
    cudaGetSymbolAddress((void**)&p_v,   g_v);
    cudaGetSymbolAddress((void**)&p_atT, g_atT);
    cudaGetSymbolAddress((void**)&p_s,   g_s);
    cudaGetSymbolAddress((void**)&p_w16, g_w16);

    cudaFuncSetAttribute(mma_gemm<1, true >, cudaFuncAttributeMaxDynamicSharedMemorySize, GEMM_SMEM_BYTES);
    cudaFuncSetAttribute(mma_gemm<2, false>, cudaFuncAttributeMaxDynamicSharedMemorySize, GEMM_SMEM_BYTES);
    cudaFuncSetAttribute(mma_gemm<4, false>, cudaFuncAttributeMaxDynamicSharedMemorySize, GEMM_SMEM_BYTES);
    cudaFuncSetAttribute(mma_gemm_big, cudaFuncAttributeMaxDynamicSharedMemorySize, BIG_SMEM);

    const long long sIC = (long long)HW * CH;   // [i][c] per-batch stride
    const long long sCI = (long long)CH * HW;   // [c][i] per-batch stride
    const long long sW  = (long long)HW * HW;

    // 1) GroupNorm + weight conversion
    gn_stats<<<BATCH * NGROUP, 256>>>(x);
    conv_w<<<CH * CH / 256, 256>>>(wq, wk, wv, wp);
    gn_apply_t<<<dim3(HW / 32, CH / 32, BATCH), dim3(32, 8)>>>(x, gs, gb);

    // 2) Q and K fused in one launch (grid.z = 8; z>>2 selects weight/bias/dst)
    dim3 gQK(CH / 128, HW / 128, 2 * BATCH);
    mma_gemm<1, true><<<gQK, 128, GEMM_SMEM_BYTES>>>(
        p_ofT, p_w16 + 0 * CH * CH, p_q, HW, CH, CH, sIC, 0, sIC, 1.0f, bq, nullptr,
        p_w16 + 1 * CH * CH, p_k, bk);
    // V: [c][j] = W x OF + bias[m]
    dim3 gV(HW / 128, CH / 128, BATCH);
    mma_gemm<2, false><<<gV, 128, GEMM_SMEM_BYTES>>>(p_w16 + 2 * CH * CH, p_ofT, p_v, CH, HW, CH, 0, sIC, sCI, 1.0f, bv, nullptr);

    // 3) scores (bf16 out): s[i,j] = (1/16) * sum_c Q[i,c] K[j,c]   (big kernel)
    dim3 gS(HW / 128, HW / 256, BATCH);
    mma_gemm_big<<<gS, 256, BIG_SMEM>>>(p_q, p_k, p_s, HW, HW, CH, sIC, sIC, sW, 0.0625f);

    // 4) softmax over j, bf16 in place
    softmax_rows<<<dim3(HW, BATCH), 256>>>(p_s);

    // 5) attn (transposed): atT[i][c] = sum_j P[i,j] V[c,j]         (big kernel)
    dim3 gA(CH / 128, HW / 256, BATCH);
    mma_gemm_big<<<gA, 256, BIG_SMEM>>>(p_s, p_v, p_atT, HW, CH, HW, sW, sCI, sIC, 1.0f);

    // 6) proj + bias + residual -> d_out
    dim3 gP(HW / 128, CH / 128, BATCH);
    mma_gemm<4, false><<<gP, 128, GEMM_SMEM_BYTES>>>(p_w16 + 3 * CH * CH, p_atT, out, CH, HW, CH, 0, sIC, sCI, 1.0f, bp, x);
}